// round 1
// baseline (speedup 1.0000x reference)
#include <cuda_runtime.h>
#include <cuda_bf16.h>
#include <math.h>

#define NBINS 256
#define NCOPIES 8            // one sub-histogram per warp (8 warps/block)
#define THREADS 256
#define BLOCKS 592           // 4 CTAs per SM on 148 SMs

__device__ unsigned int g_hist[NBINS];

__global__ void zero_kernel() {
    if (threadIdx.x < NBINS) g_hist[threadIdx.x] = 0u;
}

__global__ __launch_bounds__(THREADS) void hist_kernel(const float* __restrict__ x, int n) {
    __shared__ unsigned int sh[NCOPIES][NBINS];

    const int tid  = threadIdx.x;
    const int warp = tid >> 5;            // 0..7 -> copy index

    // zero shared sub-histograms
    #pragma unroll
    for (int c = 0; c < NCOPIES; c++)
        sh[c][tid] = 0u;
    __syncthreads();

    const float w = 0.99609375f;          // (255-0)/256, exact in fp32
    unsigned int* myhist = sh[warp];

    // vectorized main loop: float4
    const int n4 = n >> 2;
    const float4* __restrict__ x4 = (const float4*)x;
    int gid = blockIdx.x * THREADS + tid;
    const int stride = gridDim.x * THREADS;

    for (int i = gid; i < n4; i += stride) {
        float4 v = x4[i];
        #pragma unroll
        for (int k = 0; k < 4; k++) {
            float f = (k == 0) ? v.x : (k == 1) ? v.y : (k == 2) ? v.z : v.w;
            if (f >= 0.0f && f <= 255.0f) {
                int idx = (int)floorf(__fdiv_rn(f, w));
                idx = min(idx, NBINS - 1);
                atomicAdd(&myhist[idx], 1u);
            }
        }
    }

    // scalar tail (n % 4)
    for (int i = (n4 << 2) + gid; i < n; i += stride) {
        float f = x[i];
        if (f >= 0.0f && f <= 255.0f) {
            int idx = (int)floorf(__fdiv_rn(f, w));
            idx = min(idx, NBINS - 1);
            atomicAdd(&myhist[idx], 1u);
        }
    }

    __syncthreads();

    // merge the 8 copies; one thread per bin -> one global atomic per bin per block
    unsigned int total = 0;
    #pragma unroll
    for (int c = 0; c < NCOPIES; c++)
        total += sh[c][tid];
    if (total) atomicAdd(&g_hist[tid], total);
}

__global__ void finalize_kernel(const void* __restrict__ bs_ptr, float* __restrict__ out) {
    // Sniff batchsize dtype: python int 16 -> int32(16). If the buffer actually
    // holds float32, its int reinterpretation is huge (e.g. 16.0f -> 0x41800000).
    int iv = *(const int*)bs_ptr;
    float bs;
    if (iv >= 0 && iv < (1 << 24)) bs = (float)iv;
    else                           bs = *(const float*)bs_ptr;

    int i = threadIdx.x;
    float h = (float)g_hist[i];
    float h0 = (float)g_hist[0];
    out[i]         = h;          // hist
    out[NBINS + i] = bs * h0;    // count = batchsize * hist[0] broadcast
}

extern "C" void kernel_launch(void* const* d_in, const int* in_sizes, int n_in,
                              void* d_out, int out_size) {
    // identify inputs: the large buffer is the image, the size-1 buffer is batchsize
    int img_idx = 0, bs_idx = 1;
    if (n_in >= 2) {
        if (in_sizes[0] >= in_sizes[1]) { img_idx = 0; bs_idx = 1; }
        else                            { img_idx = 1; bs_idx = 0; }
    }
    const float* x = (const float*)d_in[img_idx];
    const void* bs = d_in[bs_idx];
    int n = in_sizes[img_idx];

    zero_kernel<<<1, NBINS>>>();
    hist_kernel<<<BLOCKS, THREADS>>>(x, n);
    finalize_kernel<<<1, NBINS>>>(bs, (float*)d_out);
}